// round 2
// baseline (speedup 1.0000x reference)
#include <cuda_runtime.h>
#include <math.h>

#define NSWEEP 7
#define FULL 0xffffffffu

// scratch: Y matrices (4096 x 20 x 20)
__device__ float g_Y[4096 * 400];

// ---------------------------------------------------------------------------
// Kernel A: per-batch centering + Gram + Gaussian kernel + Y = W^T K W
// grid 4096, block 256, dynamic smem 93696 B
// ---------------------------------------------------------------------------
__global__ __launch_bounds__(256) void gram_kernel(const float* __restrict__ x,
                                                   const float* __restrict__ W) {
  extern __shared__ float sm[];
  float* xm  = sm;            // 64 x 260 (padded row-major)
  float* KK  = sm + 16640;    // 64 x 65
  float* Wsm = sm + 20800;    // 64 x 20
  float* Tsm = sm + 22080;    // 64 x 20
  float* sq  = sm + 23360;    // 64

  const int b    = blockIdx.x;
  const int tid  = threadIdx.x;
  const int warp = tid >> 5;
  const int lane = tid & 31;

  for (int i = tid; i < 64 * 20; i += 256) Wsm[i] = W[i];

  // ---- load x[b], subtract per-row mean, store to padded smem ----
  const float* xb = x + (size_t)b * (64 * 256);
#pragma unroll
  for (int r8 = 0; r8 < 8; r8++) {
    const int r = warp * 8 + r8;
    const float4* row = (const float4*)(xb + r * 256);
    float4 v0 = row[lane];
    float4 v1 = row[lane + 32];
    float s = v0.x + v0.y + v0.z + v0.w + v1.x + v1.y + v1.z + v1.w;
    s += __shfl_xor_sync(FULL, s, 16);
    s += __shfl_xor_sync(FULL, s, 8);
    s += __shfl_xor_sync(FULL, s, 4);
    s += __shfl_xor_sync(FULL, s, 2);
    s += __shfl_xor_sync(FULL, s, 1);
    const float m = s * (1.0f / 256.0f);
    v0.x -= m; v0.y -= m; v0.z -= m; v0.w -= m;
    v1.x -= m; v1.y -= m; v1.z -= m; v1.w -= m;
    float4* dst = (float4*)(xm + r * 260);
    dst[lane]      = v0;
    dst[lane + 32] = v1;
  }
  __syncthreads();

  // ---- Gram: thread (tx,ty) computes gram[tx+16i][ty+16j], 4x4 tile ----
  const int tx = tid & 15;
  const int ty = tid >> 4;
  float acc[4][4];
#pragma unroll
  for (int i = 0; i < 4; i++)
#pragma unroll
    for (int j = 0; j < 4; j++) acc[i][j] = 0.f;

#pragma unroll 2
  for (int k = 0; k < 256; k += 4) {
    float4 a[4], bb[4];
#pragma unroll
    for (int i = 0; i < 4; i++)
      a[i] = *(const float4*)(xm + (tx + 16 * i) * 260 + k);
#pragma unroll
    for (int j = 0; j < 4; j++)
      bb[j] = *(const float4*)(xm + (ty + 16 * j) * 260 + k);
#pragma unroll
    for (int i = 0; i < 4; i++)
#pragma unroll
      for (int j = 0; j < 4; j++) {
        acc[i][j] = fmaf(a[i].x, bb[j].x, acc[i][j]);
        acc[i][j] = fmaf(a[i].y, bb[j].y, acc[i][j]);
        acc[i][j] = fmaf(a[i].z, bb[j].z, acc[i][j]);
        acc[i][j] = fmaf(a[i].w, bb[j].w, acc[i][j]);
      }
  }
#pragma unroll
  for (int i = 0; i < 4; i++)
#pragma unroll
    for (int j = 0; j < 4; j++)
      KK[(tx + 16 * i) * 65 + (ty + 16 * j)] = acc[i][j];
  __syncthreads();

  if (tid < 64) sq[tid] = KK[tid * 65 + tid];
  __syncthreads();

  // ---- K = exp(-50 * d2), in place ----
  for (int e = tid; e < 4096; e += 256) {
    const int c = e >> 6, d = e & 63;
    const float g = KK[c * 65 + d];
    float d2 = sq[c] + sq[d] - 2.f * g;
    d2 = fmaxf(d2, 0.f) * (1.0f / 256.0f);
    KK[c * 65 + d] = __expf(-50.f * d2);
  }
  __syncthreads();

  // ---- T = K * W (64x20) ----
  {
    const int c  = tid >> 2;
    const int d0 = (tid & 3) * 5;
    float t0 = 0, t1 = 0, t2 = 0, t3 = 0, t4 = 0;
    for (int k = 0; k < 64; k++) {
      const float kv = KK[c * 65 + k];
      const float* wr = Wsm + k * 20 + d0;
      t0 = fmaf(kv, wr[0], t0);
      t1 = fmaf(kv, wr[1], t1);
      t2 = fmaf(kv, wr[2], t2);
      t3 = fmaf(kv, wr[3], t3);
      t4 = fmaf(kv, wr[4], t4);
    }
    float* tr = Tsm + c * 20 + d0;
    tr[0] = t0; tr[1] = t1; tr[2] = t2; tr[3] = t3; tr[4] = t4;
  }
  __syncthreads();

  // ---- Y = W^T * T (20x20) -> global scratch ----
  for (int o = tid; o < 400; o += 256) {
    const int e = o / 20;
    const int f = o - 20 * e;
    float y = 0.f;
    for (int c = 0; c < 64; c++)
      y = fmaf(Wsm[c * 20 + e], Tsm[c * 20 + f], y);
    g_Y[(size_t)b * 400 + o] = y;
  }
}

// ---------------------------------------------------------------------------
// Kernel B: register-resident warp Jacobi. Lane i holds row i of A and U.
// Round-robin pairing fully unrolled -> all register indices compile-time.
// grid 1024, block 128 (4 warps, one matrix per warp)
// ---------------------------------------------------------------------------
__global__ __launch_bounds__(128) void eig_kernel(const float* __restrict__ lin_w,
                                                  const float* __restrict__ lin_b,
                                                  float* __restrict__ out) {
  __shared__ float sW[4][420];   // U * diag(logS), 20x21 padded, per warp
  __shared__ float sU[4][420];   // U

  const int warp = threadIdx.x >> 5;
  const int lane = threadIdx.x & 31;
  const int b = blockIdx.x * 4 + warp;
  const float* Yb = g_Y + (size_t)b * 400;

  float a[20], u[20];
#pragma unroll
  for (int j = 0; j < 20; j++) {
    a[j] = (lane < 20) ? Yb[lane * 20 + j] : 0.f;
    u[j] = (lane == j) ? 1.f : 0.f;
  }

  float c = 1.f, s = 0.f;
  float vpq = 1.f, vpp = 0.f, vqq = 0.f;

  for (int sw = 0; sw < NSWEEP; sw++) {
#pragma unroll
    for (int r = 0; r < 19; r++) {
      // ---- gather pre-round elements for the 10 rotation angles ----
#pragma unroll
      for (int k = 0; k < 10; k++) {
        const int uu = (k == 0) ? 0 : ((k - 1 + r) % 19) + 1;
        const int vv = ((18 - k + r) % 19) + 1;
        const int pk = uu < vv ? uu : vv;
        const int qk = uu < vv ? vv : uu;
        float gpq = __shfl_sync(FULL, a[qk], pk);  // A[p][q]
        float gpp = __shfl_sync(FULL, a[pk], pk);  // A[p][p]
        float gqq = __shfl_sync(FULL, a[qk], qk);  // A[q][q]
        if (lane == k) { vpq = gpq; vpp = gpp; vqq = gqq; }
      }
      // ---- angle (lane k computes pair k; one MUFU chain per warp) ----
      {
        float tau = (vqq - vpp) * 0.5f / vpq;
        float tt  = copysignf(1.f, tau) / (fabsf(tau) + sqrtf(fmaf(tau, tau, 1.f)));
        float cc  = rsqrtf(fmaf(tt, tt, 1.f));
        float ss  = tt * cc;
        bool ok = fabsf(vpq) > 1e-20f;
        c = ok ? cc : 1.f;
        s = ok ? ss : 0.f;
      }
      // ---- row phase: lane i combines with its partner's row ----
      {
        const int m  = (lane + 37 - r) % 19;       // slot of element lane
        int t  = (m == 18) ? 0 : ((17 - m + r) % 19) + 1;
        int kk = (m <= 8) ? m + 1 : ((m == 18) ? 0 : 18 - m);
        t  = (lane == 0) ? ((18 + r) % 19) + 1 : t;
        kk = (lane == 0) ? 0 : kk;
        const float ci = __shfl_sync(FULL, c, kk);
        const float si = __shfl_sync(FULL, s, kk);
        const float se = (lane < t) ? -si : si;
#pragma unroll
        for (int j = 0; j < 20; j++) {
          const float rt = __shfl_sync(FULL, a[j], t);
          a[j] = fmaf(se, rt, ci * a[j]);
        }
      }
      // ---- col phase: compile-time column indices; also accumulate U ----
#pragma unroll
      for (int k = 0; k < 10; k++) {
        const int uu = (k == 0) ? 0 : ((k - 1 + r) % 19) + 1;
        const int vv = ((18 - k + r) % 19) + 1;
        const int pk = uu < vv ? uu : vv;
        const int qk = uu < vv ? vv : uu;
        const float ck = __shfl_sync(FULL, c, k);
        const float sk = __shfl_sync(FULL, s, k);
        const float ap = a[pk], aq = a[qk];
        a[pk] = fmaf(-sk, aq, ck * ap);
        a[qk] = fmaf( sk, ap, ck * aq);
        const float up = u[pk], uq = u[qk];
        u[pk] = fmaf(-sk, uq, ck * up);
        u[qk] = fmaf( sk, up, ck * uq);
      }
    }
  }

  // ---- eigenvalues on diagonal: lane j's a[j]; build W = U*diag(log) ----
  if (lane < 20) {
#pragma unroll
    for (int j = 0; j < 20; j++) {
      const float lamj = __shfl_sync(FULL & 0xfffff, a[j], j);
      const float lg = __logf(fmaxf(lamj, 1e-4f));
      sW[warp][lane * 21 + j] = u[j] * lg;
      sU[warp][lane * 21 + j] = u[j];
    }
  }
  __syncwarp();

  // ---- triu(M) fused with linear head ----
  const float* Wm = sW[warp];
  const float* Um = sU[warp];
  float accv[10];
#pragma unroll
  for (int h = 0; h < 10; h++) accv[h] = 0.f;

  for (int t = lane; t < 210; t += 32) {
    int i = 0, rem = t;
    while (rem >= 20 - i) { rem -= 20 - i; i++; }
    const int k = i + rem;
    float m = 0.f;
#pragma unroll
    for (int j = 0; j < 20; j++)
      m = fmaf(Wm[i * 21 + j], Um[k * 21 + j], m);
#pragma unroll
    for (int h = 0; h < 10; h++)
      accv[h] = fmaf(m, lin_w[h * 210 + t], accv[h]);
  }
#pragma unroll
  for (int h = 0; h < 10; h++) {
    float v = accv[h];
    v += __shfl_xor_sync(FULL, v, 16);
    v += __shfl_xor_sync(FULL, v, 8);
    v += __shfl_xor_sync(FULL, v, 4);
    v += __shfl_xor_sync(FULL, v, 2);
    v += __shfl_xor_sync(FULL, v, 1);
    accv[h] = v;
  }
  if (lane == 0) {
#pragma unroll
    for (int h = 0; h < 10; h++) out[b * 10 + h] = accv[h] + lin_b[h];
  }
}

// ---------------------------------------------------------------------------
extern "C" void kernel_launch(void* const* d_in, const int* in_sizes, int n_in,
                              void* d_out, int out_size) {
  const float* x  = (const float*)d_in[0];
  const float* W  = (const float*)d_in[1];
  const float* lw = (const float*)d_in[2];
  const float* lb = (const float*)d_in[3];
  float* out = (float*)d_out;

  cudaFuncSetAttribute(gram_kernel, cudaFuncAttributeMaxDynamicSharedMemorySize,
                       23424 * sizeof(float));

  gram_kernel<<<4096, 256, 23424 * sizeof(float)>>>(x, W);
  eig_kernel<<<1024, 128>>>(lw, lb, out);
}

// round 3
// speedup vs baseline: 1.6743x; 1.6743x over previous
#include <cuda_runtime.h>
#include <math.h>

#define NSWEEP 6
#define FULL 0xffffffffu

// scratch: Y matrices (4096 x 20 x 20)
__device__ float g_Y[4096 * 400];

// ---------------------------------------------------------------------------
// Kernel A: per-batch centering + Gram + Gaussian kernel + Y = W^T K W
// grid 4096, block 256, dynamic smem 93696 B
// ---------------------------------------------------------------------------
__global__ __launch_bounds__(256) void gram_kernel(const float* __restrict__ x,
                                                   const float* __restrict__ W) {
  extern __shared__ float sm[];
  float* xm  = sm;            // 64 x 260 (padded row-major)
  float* KK  = sm + 16640;    // 64 x 65
  float* Wsm = sm + 20800;    // 64 x 20
  float* Tsm = sm + 22080;    // 64 x 20
  float* sq  = sm + 23360;    // 64

  const int b    = blockIdx.x;
  const int tid  = threadIdx.x;
  const int warp = tid >> 5;
  const int lane = tid & 31;

  for (int i = tid; i < 64 * 20; i += 256) Wsm[i] = W[i];

  const float* xb = x + (size_t)b * (64 * 256);
#pragma unroll
  for (int r8 = 0; r8 < 8; r8++) {
    const int r = warp * 8 + r8;
    const float4* row = (const float4*)(xb + r * 256);
    float4 v0 = row[lane];
    float4 v1 = row[lane + 32];
    float s = v0.x + v0.y + v0.z + v0.w + v1.x + v1.y + v1.z + v1.w;
    s += __shfl_xor_sync(FULL, s, 16);
    s += __shfl_xor_sync(FULL, s, 8);
    s += __shfl_xor_sync(FULL, s, 4);
    s += __shfl_xor_sync(FULL, s, 2);
    s += __shfl_xor_sync(FULL, s, 1);
    const float m = s * (1.0f / 256.0f);
    v0.x -= m; v0.y -= m; v0.z -= m; v0.w -= m;
    v1.x -= m; v1.y -= m; v1.z -= m; v1.w -= m;
    float4* dst = (float4*)(xm + r * 260);
    dst[lane]      = v0;
    dst[lane + 32] = v1;
  }
  __syncthreads();

  const int tx = tid & 15;
  const int ty = tid >> 4;
  float acc[4][4];
#pragma unroll
  for (int i = 0; i < 4; i++)
#pragma unroll
    for (int j = 0; j < 4; j++) acc[i][j] = 0.f;

#pragma unroll 2
  for (int k = 0; k < 256; k += 4) {
    float4 a[4], bb[4];
#pragma unroll
    for (int i = 0; i < 4; i++)
      a[i] = *(const float4*)(xm + (tx + 16 * i) * 260 + k);
#pragma unroll
    for (int j = 0; j < 4; j++)
      bb[j] = *(const float4*)(xm + (ty + 16 * j) * 260 + k);
#pragma unroll
    for (int i = 0; i < 4; i++)
#pragma unroll
      for (int j = 0; j < 4; j++) {
        acc[i][j] = fmaf(a[i].x, bb[j].x, acc[i][j]);
        acc[i][j] = fmaf(a[i].y, bb[j].y, acc[i][j]);
        acc[i][j] = fmaf(a[i].z, bb[j].z, acc[i][j]);
        acc[i][j] = fmaf(a[i].w, bb[j].w, acc[i][j]);
      }
  }
#pragma unroll
  for (int i = 0; i < 4; i++)
#pragma unroll
    for (int j = 0; j < 4; j++)
      KK[(tx + 16 * i) * 65 + (ty + 16 * j)] = acc[i][j];
  __syncthreads();

  if (tid < 64) sq[tid] = KK[tid * 65 + tid];
  __syncthreads();

  for (int e = tid; e < 4096; e += 256) {
    const int c = e >> 6, d = e & 63;
    const float g = KK[c * 65 + d];
    float d2 = sq[c] + sq[d] - 2.f * g;
    d2 = fmaxf(d2, 0.f) * (1.0f / 256.0f);
    KK[c * 65 + d] = __expf(-50.f * d2);
  }
  __syncthreads();

  {
    const int c  = tid >> 2;
    const int d0 = (tid & 3) * 5;
    float t0 = 0, t1 = 0, t2 = 0, t3 = 0, t4 = 0;
    for (int k = 0; k < 64; k++) {
      const float kv = KK[c * 65 + k];
      const float* wr = Wsm + k * 20 + d0;
      t0 = fmaf(kv, wr[0], t0);
      t1 = fmaf(kv, wr[1], t1);
      t2 = fmaf(kv, wr[2], t2);
      t3 = fmaf(kv, wr[3], t3);
      t4 = fmaf(kv, wr[4], t4);
    }
    float* tr = Tsm + c * 20 + d0;
    tr[0] = t0; tr[1] = t1; tr[2] = t2; tr[3] = t3; tr[4] = t4;
  }
  __syncthreads();

  for (int o = tid; o < 400; o += 256) {
    const int e = o / 20;
    const int f = o - 20 * e;
    float y = 0.f;
    for (int c = 0; c < 64; c++)
      y = fmaf(Wsm[c * 20 + e], Tsm[c * 20 + f], y);
    g_Y[(size_t)b * 400 + o] = y;
  }
}

// ---------------------------------------------------------------------------
// Kernel B: register-resident warp Jacobi with LOCAL angle computation.
// Lane i holds row i of A and U plus its own diagonal dg.
// Per round: partner t analytic; angle computed redundantly on both pair
// lanes from bitwise-identical inputs (dg, shfl(dg,t), symmetrized apq).
// grid 1024, block 128.
// ---------------------------------------------------------------------------
__global__ __launch_bounds__(128, 3) void eig_kernel(const float* __restrict__ lin_w,
                                                     const float* __restrict__ lin_b,
                                                     float* __restrict__ out) {
  __shared__ float sW[4][420];   // U * diag(logS), 20x21 padded, per warp
  __shared__ float sU[4][420];   // U

  const int warp = threadIdx.x >> 5;
  const int lane = threadIdx.x & 31;
  const int b = blockIdx.x * 4 + warp;
  const float* Yb = g_Y + (size_t)b * 400;

  float a[20], u[20];
#pragma unroll
  for (int j = 0; j < 20; j++) {
    a[j] = (lane < 20) ? Yb[lane * 20 + j] : 0.f;
    u[j] = (lane == j) ? 1.f : 0.f;
  }
  float dg = (lane < 20) ? Yb[lane * 20 + lane] : 0.f;

  for (int sw = 0; sw < NSWEEP; sw++) {
#pragma unroll
    for (int r = 0; r < 19; r++) {
      // ---- partner of this lane in round r (tournament schedule) ----
      const int m = (lane + 37 - r) % 19;
      int t = (m == 18) ? 0 : ((17 - m + r) % 19) + 1;
      t = (lane == 0) ? ((18 + r) % 19) + 1 : t;
      const bool isp = lane < t;   // am I the smaller index of the pair?

      // ---- apq = A[lane][t] via 4-chain select tree ----
      float s0 = 0.f, s1 = 0.f, s2 = 0.f, s3 = 0.f;
#pragma unroll
      for (int j = 0; j < 5; j++)  s0 = (t == j)      ? a[j]      : s0;
#pragma unroll
      for (int j = 0; j < 5; j++)  s1 = (t == j + 5)  ? a[j + 5]  : s1;
#pragma unroll
      for (int j = 0; j < 5; j++)  s2 = (t == j + 10) ? a[j + 10] : s2;
#pragma unroll
      for (int j = 0; j < 5; j++)  s3 = (t == j + 15) ? a[j + 15] : s3;
      const float apq_own = (s0 + s1) + (s2 + s3);

      // ---- symmetrize so both pair lanes see identical bits ----
      const float att = __shfl_sync(FULL, dg, t);
      const float apq = 0.5f * (apq_own + __shfl_sync(FULL, apq_own, t));

      // ---- angle (identical on lanes p and q) ----
      const float app = isp ? dg : att;
      const float aqq = isp ? att : dg;
      float c, s, tg;
      {
        const float tau = (aqq - app) * (0.5f / apq);
        const float tt  = copysignf(1.f, tau) / (fabsf(tau) + sqrtf(fmaf(tau, tau, 1.f)));
        const float cc  = rsqrtf(fmaf(tt, tt, 1.f));
        const float ss  = tt * cc;
        const bool ok = (fabsf(apq) > 1e-20f) && (lane < 20);
        c  = ok ? cc : 1.f;
        s  = ok ? ss : 0.f;
        tg = ok ? tt : 0.f;
      }

      // ---- exact diagonal update (Rutishauser) ----
      dg = fmaf(isp ? -tg : tg, apq, dg);

      // ---- row phase: lane combines its row with partner's row ----
      {
        const float se = isp ? -s : s;
#pragma unroll
        for (int j = 0; j < 20; j++) {
          const float rt = __shfl_sync(FULL, a[j], t);
          a[j] = fmaf(se, rt, c * a[j]);
        }
      }

      // ---- col phase: compile-time pair columns; also accumulate U ----
#pragma unroll
      for (int k = 0; k < 10; k++) {
        const int uu = (k == 0) ? 0 : ((k - 1 + r) % 19) + 1;
        const int vv = ((18 - k + r) % 19) + 1;
        const int pk = uu < vv ? uu : vv;
        const int qk = uu < vv ? vv : uu;
        const float ck = __shfl_sync(FULL, c, pk);
        const float sk = __shfl_sync(FULL, s, pk);
        const float ap = a[pk], aq = a[qk];
        a[pk] = fmaf(-sk, aq, ck * ap);
        a[qk] = fmaf( sk, ap, ck * aq);
        const float up = u[pk], uq = u[qk];
        u[pk] = fmaf(-sk, uq, ck * up);
        u[qk] = fmaf( sk, up, ck * uq);
      }
    }
  }

  // ---- exact eigenvalue from converged diagonal of a[] ----
  float lam = 0.f;
#pragma unroll
  for (int j = 0; j < 20; j++) lam = (lane == j) ? a[j] : lam;
  const float lg_own = __logf(fmaxf(lam, 1e-4f));

  // ---- W = U*diag(logS), U -> smem ----
  if (lane < 20) {
#pragma unroll
    for (int j = 0; j < 20; j++) {
      const float lgj = __shfl_sync(FULL, lg_own, j);
      sW[warp][lane * 21 + j] = u[j] * lgj;
      sU[warp][lane * 21 + j] = u[j];
    }
  } else {
#pragma unroll
    for (int j = 0; j < 20; j++) (void)__shfl_sync(FULL, lg_own, j);
  }
  __syncwarp();

  // ---- triu(M) fused with linear head ----
  const float* Wm = sW[warp];
  const float* Um = sU[warp];
  float accv[10];
#pragma unroll
  for (int h = 0; h < 10; h++) accv[h] = 0.f;

  for (int t = lane; t < 210; t += 32) {
    int i = 0, rem = t;
    while (rem >= 20 - i) { rem -= 20 - i; i++; }
    const int k = i + rem;
    float mm = 0.f;
#pragma unroll
    for (int j = 0; j < 20; j++)
      mm = fmaf(Wm[i * 21 + j], Um[k * 21 + j], mm);
#pragma unroll
    for (int h = 0; h < 10; h++)
      accv[h] = fmaf(mm, lin_w[h * 210 + t], accv[h]);
  }
#pragma unroll
  for (int h = 0; h < 10; h++) {
    float v = accv[h];
    v += __shfl_xor_sync(FULL, v, 16);
    v += __shfl_xor_sync(FULL, v, 8);
    v += __shfl_xor_sync(FULL, v, 4);
    v += __shfl_xor_sync(FULL, v, 2);
    v += __shfl_xor_sync(FULL, v, 1);
    accv[h] = v;
  }
  if (lane == 0) {
#pragma unroll
    for (int h = 0; h < 10; h++) out[b * 10 + h] = accv[h] + lin_b[h];
  }
}

// ---------------------------------------------------------------------------
extern "C" void kernel_launch(void* const* d_in, const int* in_sizes, int n_in,
                              void* d_out, int out_size) {
  const float* x  = (const float*)d_in[0];
  const float* W  = (const float*)d_in[1];
  const float* lw = (const float*)d_in[2];
  const float* lb = (const float*)d_in[3];
  float* out = (float*)d_out;

  cudaFuncSetAttribute(gram_kernel, cudaFuncAttributeMaxDynamicSharedMemorySize,
                       23424 * sizeof(float));

  gram_kernel<<<4096, 256, 23424 * sizeof(float)>>>(x, W);
  eig_kernel<<<1024, 128>>>(lw, lb, out);
}

// round 4
// speedup vs baseline: 1.8964x; 1.1327x over previous
#include <cuda_runtime.h>
#include <math.h>

#define NSWEEP 5
#define FULL 0xffffffffu

// scratch: Y matrices (4096 x 20 x 20)
__device__ float g_Y[4096 * 400];

// ---------------------------------------------------------------------------
// Kernel A: per-batch centering + Gram + Gaussian kernel + Y = W^T K W
// grid 4096, block 256, dynamic smem 93696 B
// Gram exploits symmetry: only register-tile blocks with i<=j computed.
// ---------------------------------------------------------------------------
__global__ __launch_bounds__(256) void gram_kernel(const float* __restrict__ x,
                                                   const float* __restrict__ W) {
  extern __shared__ float sm[];
  float* xm  = sm;            // 64 x 260 (padded row-major)
  float* KK  = sm + 16640;    // 64 x 65
  float* Wsm = sm + 20800;    // 64 x 20
  float* Tsm = sm + 22080;    // 64 x 20
  float* sq  = sm + 23360;    // 64

  const int b    = blockIdx.x;
  const int tid  = threadIdx.x;
  const int warp = tid >> 5;
  const int lane = tid & 31;

  for (int i = tid; i < 64 * 20; i += 256) Wsm[i] = W[i];

  const float* xb = x + (size_t)b * (64 * 256);
#pragma unroll
  for (int r8 = 0; r8 < 8; r8++) {
    const int r = warp * 8 + r8;
    const float4* row = (const float4*)(xb + r * 256);
    float4 v0 = row[lane];
    float4 v1 = row[lane + 32];
    float s = v0.x + v0.y + v0.z + v0.w + v1.x + v1.y + v1.z + v1.w;
    s += __shfl_xor_sync(FULL, s, 16);
    s += __shfl_xor_sync(FULL, s, 8);
    s += __shfl_xor_sync(FULL, s, 4);
    s += __shfl_xor_sync(FULL, s, 2);
    s += __shfl_xor_sync(FULL, s, 1);
    const float m = s * (1.0f / 256.0f);
    v0.x -= m; v0.y -= m; v0.z -= m; v0.w -= m;
    v1.x -= m; v1.y -= m; v1.z -= m; v1.w -= m;
    float4* dst = (float4*)(xm + r * 260);
    dst[lane]      = v0;
    dst[lane + 32] = v1;
  }
  __syncthreads();

  const int tx = tid & 15;
  const int ty = tid >> 4;
  float acc[4][4];   // only i<=j used
#pragma unroll
  for (int i = 0; i < 4; i++)
#pragma unroll
    for (int j = 0; j < 4; j++) acc[i][j] = 0.f;

#pragma unroll 2
  for (int k = 0; k < 256; k += 4) {
    float4 a[4], bb[4];
#pragma unroll
    for (int i = 0; i < 4; i++)
      a[i] = *(const float4*)(xm + (tx + 16 * i) * 260 + k);
#pragma unroll
    for (int j = 0; j < 4; j++)
      bb[j] = *(const float4*)(xm + (ty + 16 * j) * 260 + k);
#pragma unroll
    for (int i = 0; i < 4; i++)
#pragma unroll
      for (int j = 0; j < 4; j++) {
        if (j >= i) {
          acc[i][j] = fmaf(a[i].x, bb[j].x, acc[i][j]);
          acc[i][j] = fmaf(a[i].y, bb[j].y, acc[i][j]);
          acc[i][j] = fmaf(a[i].z, bb[j].z, acc[i][j]);
          acc[i][j] = fmaf(a[i].w, bb[j].w, acc[i][j]);
        }
      }
  }
#pragma unroll
  for (int i = 0; i < 4; i++)
#pragma unroll
    for (int j = 0; j < 4; j++) {
      if (j >= i) {
        const int c = tx + 16 * i;
        const int d = ty + 16 * j;
        KK[c * 65 + d] = acc[i][j];
        if (j > i) KK[d * 65 + c] = acc[i][j];   // mirror block
      }
    }
  __syncthreads();

  if (tid < 64) sq[tid] = KK[tid * 65 + tid];
  __syncthreads();

  for (int e = tid; e < 4096; e += 256) {
    const int c = e >> 6, d = e & 63;
    const float g = KK[c * 65 + d];
    float d2 = sq[c] + sq[d] - 2.f * g;
    d2 = fmaxf(d2, 0.f) * (1.0f / 256.0f);
    KK[c * 65 + d] = __expf(-50.f * d2);
  }
  __syncthreads();

  {
    const int c  = tid >> 2;
    const int d0 = (tid & 3) * 5;
    float t0 = 0, t1 = 0, t2 = 0, t3 = 0, t4 = 0;
    for (int k = 0; k < 64; k++) {
      const float kv = KK[c * 65 + k];
      const float* wr = Wsm + k * 20 + d0;
      t0 = fmaf(kv, wr[0], t0);
      t1 = fmaf(kv, wr[1], t1);
      t2 = fmaf(kv, wr[2], t2);
      t3 = fmaf(kv, wr[3], t3);
      t4 = fmaf(kv, wr[4], t4);
    }
    float* tr = Tsm + c * 20 + d0;
    tr[0] = t0; tr[1] = t1; tr[2] = t2; tr[3] = t3; tr[4] = t4;
  }
  __syncthreads();

  for (int o = tid; o < 400; o += 256) {
    const int e = o / 20;
    const int f = o - 20 * e;
    float y = 0.f;
    for (int c = 0; c < 64; c++)
      y = fmaf(Wsm[c * 20 + e], Tsm[c * 20 + f], y);
    g_Y[(size_t)b * 400 + o] = y;
  }
}

// ---------------------------------------------------------------------------
// Kernel B: register-resident warp Jacobi, local angles, 5 sweeps.
// launch_bounds(128,4): cap regs at 128 for 16 warps/SM.
// ---------------------------------------------------------------------------
__global__ __launch_bounds__(128, 4) void eig_kernel(const float* __restrict__ lin_w,
                                                     const float* __restrict__ lin_b,
                                                     float* __restrict__ out) {
  __shared__ float sW[4][420];   // U * diag(logS), 20x21 padded, per warp
  __shared__ float sU[4][420];   // U

  const int warp = threadIdx.x >> 5;
  const int lane = threadIdx.x & 31;
  const int b = blockIdx.x * 4 + warp;
  const float* Yb = g_Y + (size_t)b * 400;

  float a[20], u[20];
#pragma unroll
  for (int j = 0; j < 20; j++) {
    a[j] = (lane < 20) ? Yb[lane * 20 + j] : 0.f;
    u[j] = (lane == j) ? 1.f : 0.f;
  }
  float dg = (lane < 20) ? Yb[lane * 20 + lane] : 0.f;

  for (int sw = 0; sw < NSWEEP; sw++) {
#pragma unroll
    for (int r = 0; r < 19; r++) {
      // ---- partner of this lane in round r (tournament schedule) ----
      const int m = (lane + 37 - r) % 19;
      int t = (m == 18) ? 0 : ((17 - m + r) % 19) + 1;
      t = (lane == 0) ? ((18 + r) % 19) + 1 : t;
      const bool isp = lane < t;

      // ---- apq = A[lane][t] via 4-chain select tree ----
      float s0 = 0.f, s1 = 0.f, s2 = 0.f, s3 = 0.f;
#pragma unroll
      for (int j = 0; j < 5; j++)  s0 = (t == j)      ? a[j]      : s0;
#pragma unroll
      for (int j = 0; j < 5; j++)  s1 = (t == j + 5)  ? a[j + 5]  : s1;
#pragma unroll
      for (int j = 0; j < 5; j++)  s2 = (t == j + 10) ? a[j + 10] : s2;
#pragma unroll
      for (int j = 0; j < 5; j++)  s3 = (t == j + 15) ? a[j + 15] : s3;
      const float apq_own = (s0 + s1) + (s2 + s3);

      // ---- symmetrize so both pair lanes see identical bits ----
      const float att = __shfl_sync(FULL, dg, t);
      const float apq = 0.5f * (apq_own + __shfl_sync(FULL, apq_own, t));

      // ---- angle (identical on lanes p and q) ----
      const float app = isp ? dg : att;
      const float aqq = isp ? att : dg;
      float c, s, tg;
      {
        const float tau = (aqq - app) * (0.5f / apq);
        const float tt  = copysignf(1.f, tau) / (fabsf(tau) + sqrtf(fmaf(tau, tau, 1.f)));
        const float cc  = rsqrtf(fmaf(tt, tt, 1.f));
        const float ss  = tt * cc;
        const bool ok = (fabsf(apq) > 1e-20f) && (lane < 20);
        c  = ok ? cc : 1.f;
        s  = ok ? ss : 0.f;
        tg = ok ? tt : 0.f;
      }

      // ---- exact diagonal update (Rutishauser) ----
      dg = fmaf(isp ? -tg : tg, apq, dg);

      // ---- row phase ----
      {
        const float se = isp ? -s : s;
#pragma unroll
        for (int j = 0; j < 20; j++) {
          const float rt = __shfl_sync(FULL, a[j], t);
          a[j] = fmaf(se, rt, c * a[j]);
        }
      }

      // ---- col phase: compile-time pair columns; accumulate U ----
#pragma unroll
      for (int k = 0; k < 10; k++) {
        const int uu = (k == 0) ? 0 : ((k - 1 + r) % 19) + 1;
        const int vv = ((18 - k + r) % 19) + 1;
        const int pk = uu < vv ? uu : vv;
        const int qk = uu < vv ? vv : uu;
        const float ck = __shfl_sync(FULL, c, pk);
        const float sk = __shfl_sync(FULL, s, pk);
        const float ap = a[pk], aq = a[qk];
        a[pk] = fmaf(-sk, aq, ck * ap);
        a[qk] = fmaf( sk, ap, ck * aq);
        const float up = u[pk], uq = u[qk];
        u[pk] = fmaf(-sk, uq, ck * up);
        u[qk] = fmaf( sk, up, ck * uq);
      }
    }
  }

  // ---- exact eigenvalue from converged diagonal of a[] ----
  float lam = 0.f;
#pragma unroll
  for (int j = 0; j < 20; j++) lam = (lane == j) ? a[j] : lam;
  const float lg_own = __logf(fmaxf(lam, 1e-4f));

  // ---- W = U*diag(logS), U -> smem ----
#pragma unroll
  for (int j = 0; j < 20; j++) {
    const float lgj = __shfl_sync(FULL, lg_own, j);
    if (lane < 20) {
      sW[warp][lane * 21 + j] = u[j] * lgj;
      sU[warp][lane * 21 + j] = u[j];
    }
  }
  __syncwarp();

  // ---- triu(M) fused with linear head ----
  const float* Wm = sW[warp];
  const float* Um = sU[warp];
  float accv[10];
#pragma unroll
  for (int h = 0; h < 10; h++) accv[h] = 0.f;

  for (int t = lane; t < 210; t += 32) {
    // closed-form row index for triu(20): i s.t. start(i)<=t<start(i+1),
    // start(i) = 20i - i(i-1)/2
    int i = (int)((41.0f - sqrtf(fmaf(-8.f, (float)t, 1681.0f))) * 0.5f);
    int st = 20 * i - ((i * (i - 1)) >> 1);
    if (st > t) { i--; st = 20 * i - ((i * (i - 1)) >> 1); }
    else if (t >= st + (20 - i)) { st += 20 - i; i++; }
    const int k = i + (t - st);
    float mm = 0.f;
#pragma unroll
    for (int j = 0; j < 20; j++)
      mm = fmaf(Wm[i * 21 + j], Um[k * 21 + j], mm);
#pragma unroll
    for (int h = 0; h < 10; h++)
      accv[h] = fmaf(mm, lin_w[h * 210 + t], accv[h]);
  }
#pragma unroll
  for (int h = 0; h < 10; h++) {
    float v = accv[h];
    v += __shfl_xor_sync(FULL, v, 16);
    v += __shfl_xor_sync(FULL, v, 8);
    v += __shfl_xor_sync(FULL, v, 4);
    v += __shfl_xor_sync(FULL, v, 2);
    v += __shfl_xor_sync(FULL, v, 1);
    accv[h] = v;
  }
  if (lane == 0) {
#pragma unroll
    for (int h = 0; h < 10; h++) out[b * 10 + h] = accv[h] + lin_b[h];
  }
}

// ---------------------------------------------------------------------------
extern "C" void kernel_launch(void* const* d_in, const int* in_sizes, int n_in,
                              void* d_out, int out_size) {
  const float* x  = (const float*)d_in[0];
  const float* W  = (const float*)d_in[1];
  const float* lw = (const float*)d_in[2];
  const float* lb = (const float*)d_in[3];
  float* out = (float*)d_out;

  cudaFuncSetAttribute(gram_kernel, cudaFuncAttributeMaxDynamicSharedMemorySize,
                       23424 * sizeof(float));

  gram_kernel<<<4096, 256, 23424 * sizeof(float)>>>(x, W);
  eig_kernel<<<1024, 128>>>(lw, lb, out);
}

// round 8
// speedup vs baseline: 2.5036x; 1.3202x over previous
#include <cuda_runtime.h>
#include <cuda_bf16.h>
#include <cstdint>
#include <math.h>

#define NSWEEP 5
#define FULL 0xffffffffu

// scratch: Y matrices (4096 x 20 x 20)
__device__ float g_Y[4096 * 400];

// ---------------------------------------------------------------------------
// helpers
// ---------------------------------------------------------------------------
__device__ __forceinline__ uint32_t s2u(const void* p) {
  return (uint32_t)__cvta_generic_to_shared(p);
}

__device__ __forceinline__ void ldsm4(uint32_t addr, uint32_t* r) {
  asm volatile("ldmatrix.sync.aligned.m8n8.x4.shared.b16 {%0,%1,%2,%3}, [%4];"
               : "=r"(r[0]), "=r"(r[1]), "=r"(r[2]), "=r"(r[3]) : "r"(addr));
}
__device__ __forceinline__ void mma16816(float* d, const uint32_t* a,
                                         uint32_t b0, uint32_t b1) {
  asm volatile(
      "mma.sync.aligned.m16n8k16.row.col.f32.bf16.bf16.f32 "
      "{%0,%1,%2,%3},{%4,%5,%6,%7},{%8,%9},{%0,%1,%2,%3};"
      : "+f"(d[0]), "+f"(d[1]), "+f"(d[2]), "+f"(d[3])
      : "r"(a[0]), "r"(a[1]), "r"(a[2]), "r"(a[3]), "r"(b0), "r"(b1));
}

// ---------------------------------------------------------------------------
// Kernel A: centering + tensor-core Gram (bf16 3-split) + exp + Y = W^T K W
// grid 4096, block 256, dyn smem 94720 B
// byte layout: Xh[0,33792) Xl[33792,67584) KK[67584,84224)
//              Wsm[84224,89344) Tsm[89344,94464) sq[94464,94720)
// ---------------------------------------------------------------------------
__global__ __launch_bounds__(256) void gram_kernel(const float* __restrict__ x,
                                                   const float* __restrict__ W) {
  extern __shared__ char smc[];
  __nv_bfloat16* Xh = (__nv_bfloat16*)smc;            // 64 x 264
  __nv_bfloat16* Xl = Xh + 64 * 264;                  // 64 x 264
  float* KK  = (float*)(smc + 67584);                 // 64 x 65
  float* Wsm = (float*)(smc + 84224);                 // 64 x 20
  float* Tsm = (float*)(smc + 89344);                 // 64 x 20
  float* sq  = (float*)(smc + 94464);                 // 64

  const int b    = blockIdx.x;
  const int tid  = threadIdx.x;
  const int warp = tid >> 5;
  const int lane = tid & 31;

  for (int i = tid; i < 64 * 20; i += 256) Wsm[i] = W[i];

  // ---- load x[b], center, split into bf16 hi/lo ----
  const float* xb = x + (size_t)b * (64 * 256);
#pragma unroll
  for (int r8 = 0; r8 < 8; r8++) {
    const int r = warp * 8 + r8;
    const float4* row = (const float4*)(xb + r * 256);
    float4 v0 = row[lane];
    float4 v1 = row[lane + 32];
    float s = v0.x + v0.y + v0.z + v0.w + v1.x + v1.y + v1.z + v1.w;
    s += __shfl_xor_sync(FULL, s, 16);
    s += __shfl_xor_sync(FULL, s, 8);
    s += __shfl_xor_sync(FULL, s, 4);
    s += __shfl_xor_sync(FULL, s, 2);
    s += __shfl_xor_sync(FULL, s, 1);
    const float m = s * (1.0f / 256.0f);
    v0.x -= m; v0.y -= m; v0.z -= m; v0.w -= m;
    v1.x -= m; v1.y -= m; v1.z -= m; v1.w -= m;

    __nv_bfloat162* ph0 = (__nv_bfloat162*)(Xh + r * 264 + 4 * lane);
    __nv_bfloat162* pl0 = (__nv_bfloat162*)(Xl + r * 264 + 4 * lane);
    __nv_bfloat162* ph1 = (__nv_bfloat162*)(Xh + r * 264 + 128 + 4 * lane);
    __nv_bfloat162* pl1 = (__nv_bfloat162*)(Xl + r * 264 + 128 + 4 * lane);

    __nv_bfloat162 h;
    h = __floats2bfloat162_rn(v0.x, v0.y);
    ph0[0] = h;
    pl0[0] = __floats2bfloat162_rn(v0.x - __bfloat162float(h.x),
                                   v0.y - __bfloat162float(h.y));
    h = __floats2bfloat162_rn(v0.z, v0.w);
    ph0[1] = h;
    pl0[1] = __floats2bfloat162_rn(v0.z - __bfloat162float(h.x),
                                   v0.w - __bfloat162float(h.y));
    h = __floats2bfloat162_rn(v1.x, v1.y);
    ph1[0] = h;
    pl1[0] = __floats2bfloat162_rn(v1.x - __bfloat162float(h.x),
                                   v1.y - __bfloat162float(h.y));
    h = __floats2bfloat162_rn(v1.z, v1.w);
    ph1[1] = h;
    pl1[1] = __floats2bfloat162_rn(v1.z - __bfloat162float(h.x),
                                   v1.w - __bfloat162float(h.y));
  }
  __syncthreads();

  // ---- Gram via mma: warp handles blocks (bi,bj) and (bi+32,bj) ----
  {
    const int bj = (warp & 3) * 16;
    const int bi = (warp >> 2) * 16;
    const int mrow = lane & 7;
    const int msel = lane >> 3;
    const int cofs = (msel >> 1) * 8;
    const int rsel = (msel & 1) * 8;
    const uint32_t LOFF = 64 * 264 * 2;  // bytes Xh -> Xl

    uint32_t aA0 = s2u(Xh + (bi + rsel + mrow) * 264 + cofs);
    uint32_t aA1 = aA0 + 32 * 264 * 2;
    uint32_t aB  = s2u(Xh + (bj + rsel + mrow) * 264 + cofs);

    float c0[8], c1[8];
#pragma unroll
    for (int i = 0; i < 8; i++) { c0[i] = 0.f; c1[i] = 0.f; }

#pragma unroll 4
    for (int kc = 0; kc < 16; kc++) {
      uint32_t Ah[4], Al[4], Bh[4], Bl[4], A1h[4], A1l[4];
      ldsm4(aA0, Ah);  ldsm4(aA0 + LOFF, Al);
      ldsm4(aA1, A1h); ldsm4(aA1 + LOFF, A1l);
      ldsm4(aB, Bh);   ldsm4(aB + LOFF, Bl);

      mma16816(c0,     Ah,  Bh[0], Bh[2]);
      mma16816(c0,     Ah,  Bl[0], Bl[2]);
      mma16816(c0,     Al,  Bh[0], Bh[2]);
      mma16816(c0 + 4, Ah,  Bh[1], Bh[3]);
      mma16816(c0 + 4, Ah,  Bl[1], Bl[3]);
      mma16816(c0 + 4, Al,  Bh[1], Bh[3]);

      mma16816(c1,     A1h, Bh[0], Bh[2]);
      mma16816(c1,     A1h, Bl[0], Bl[2]);
      mma16816(c1,     A1l, Bh[0], Bh[2]);
      mma16816(c1 + 4, A1h, Bh[1], Bh[3]);
      mma16816(c1 + 4, A1h, Bl[1], Bl[3]);
      mma16816(c1 + 4, A1l, Bh[1], Bh[3]);

      aA0 += 32; aA1 += 32; aB += 32;
    }

    const int r0 = lane >> 2;
    const int cb = 2 * (lane & 3);
    float* K0 = KK + (bi + r0) * 65 + bj + cb;
    K0[0] = c0[0];  K0[1] = c0[1];
    K0[8 * 65] = c0[2];  K0[8 * 65 + 1] = c0[3];
    K0[8] = c0[4];  K0[9] = c0[5];
    K0[8 * 65 + 8] = c0[6];  K0[8 * 65 + 9] = c0[7];
    float* K1 = KK + (bi + 32 + r0) * 65 + bj + cb;
    K1[0] = c1[0];  K1[1] = c1[1];
    K1[8 * 65] = c1[2];  K1[8 * 65 + 1] = c1[3];
    K1[8] = c1[4];  K1[9] = c1[5];
    K1[8 * 65 + 8] = c1[6];  K1[8 * 65 + 9] = c1[7];
  }
  __syncthreads();

  if (tid < 64) sq[tid] = KK[tid * 65 + tid];
  __syncthreads();

  // ---- K = exp(-50 * d2), in place ----
  for (int e = tid; e < 4096; e += 256) {
    const int c = e >> 6, d = e & 63;
    const float g = KK[c * 65 + d];
    float d2 = sq[c] + sq[d] - 2.f * g;
    d2 = fmaxf(d2, 0.f) * (1.0f / 256.0f);
    KK[c * 65 + d] = __expf(-50.f * d2);
  }
  __syncthreads();

  // ---- T = K * W (64x20) ----
  {
    const int c  = tid >> 2;
    const int d0 = (tid & 3) * 5;
    float t0 = 0, t1 = 0, t2 = 0, t3 = 0, t4 = 0;
    for (int k = 0; k < 64; k++) {
      const float kv = KK[c * 65 + k];
      const float* wr = Wsm + k * 20 + d0;
      t0 = fmaf(kv, wr[0], t0);
      t1 = fmaf(kv, wr[1], t1);
      t2 = fmaf(kv, wr[2], t2);
      t3 = fmaf(kv, wr[3], t3);
      t4 = fmaf(kv, wr[4], t4);
    }
    float* tr = Tsm + c * 20 + d0;
    tr[0] = t0; tr[1] = t1; tr[2] = t2; tr[3] = t3; tr[4] = t4;
  }
  __syncthreads();

  // ---- Y = W^T * T (20x20) -> global scratch ----
  for (int o = tid; o < 400; o += 256) {
    const int e = o / 20;
    const int f = o - 20 * e;
    float y = 0.f;
    for (int c = 0; c < 64; c++)
      y = fmaf(Wsm[c * 20 + e], Tsm[c * 20 + f], y);
    g_Y[(size_t)b * 400 + o] = y;
  }
}

// ---------------------------------------------------------------------------
// Kernel B: register-resident warp Jacobi, local angles, incremental schedule.
// ---------------------------------------------------------------------------
__global__ __launch_bounds__(128, 4) void eig_kernel(const float* __restrict__ lin_w,
                                                     const float* __restrict__ lin_b,
                                                     float* __restrict__ out) {
  __shared__ float sW[4][420];
  __shared__ float sU[4][420];

  const int warp = threadIdx.x >> 5;
  const int lane = threadIdx.x & 31;
  const int b = blockIdx.x * 4 + warp;
  const float* Yb = g_Y + (size_t)b * 400;

  float a[20], u[20];
#pragma unroll
  for (int j = 0; j < 20; j++) {
    a[j] = (lane < 20) ? Yb[lane * 20 + j] : 0.f;
    u[j] = (lane == j) ? 1.f : 0.f;
  }
  float dg = (lane < 20) ? Yb[lane * 20 + lane] : 0.f;

  int m = (lane + 37) % 19;   // schedule slot, maintained incrementally

  for (int sw = 0; sw < NSWEEP; sw++) {
#pragma unroll
    for (int r = 0; r < 19; r++) {
      // ---- partner: t = (m==18)?0 : ((2r-1-lane) mod 19)+1 ; lane0 -> D ----
      const int C = (2 * r + 18) % 19;        // compile-time
      const int D = ((18 + r) % 19) + 1;      // compile-time
      int uu = C - lane;
      uu += (uu < 0) ? 19 : 0;
      uu += (uu < 0) ? 19 : 0;
      int t = (m == 18) ? 0 : uu + 1;
      t = (lane == 0) ? D : t;
      const bool isp = lane < t;

      // ---- apq = A[lane][t] via 4-chain select tree ----
      float s0 = 0.f, s1 = 0.f, s2 = 0.f, s3 = 0.f;
#pragma unroll
      for (int j = 0; j < 5; j++)  s0 = (t == j)      ? a[j]      : s0;
#pragma unroll
      for (int j = 0; j < 5; j++)  s1 = (t == j + 5)  ? a[j + 5]  : s1;
#pragma unroll
      for (int j = 0; j < 5; j++)  s2 = (t == j + 10) ? a[j + 10] : s2;
#pragma unroll
      for (int j = 0; j < 5; j++)  s3 = (t == j + 15) ? a[j + 15] : s3;
      const float apq_own = (s0 + s1) + (s2 + s3);

      const float att = __shfl_sync(FULL, dg, t);
      const float apq = 0.5f * (apq_own + __shfl_sync(FULL, apq_own, t));

      const float app = isp ? dg : att;
      const float aqq = isp ? att : dg;
      float c, s, tg;
      {
        const float tau = (aqq - app) * (0.5f / apq);
        const float tt  = copysignf(1.f, tau) / (fabsf(tau) + sqrtf(fmaf(tau, tau, 1.f)));
        const float cc  = rsqrtf(fmaf(tt, tt, 1.f));
        const float ss  = tt * cc;
        const bool ok = (fabsf(apq) > 1e-20f) && (lane < 20);
        c  = ok ? cc : 1.f;
        s  = ok ? ss : 0.f;
        tg = ok ? tt : 0.f;
      }

      dg = fmaf(isp ? -tg : tg, apq, dg);

      // ---- row phase ----
      {
        const float se = isp ? -s : s;
#pragma unroll
        for (int j = 0; j < 20; j++) {
          const float rt = __shfl_sync(FULL, a[j], t);
          a[j] = fmaf(se, rt, c * a[j]);
        }
      }

      // ---- col phase ----
#pragma unroll
      for (int k = 0; k < 10; k++) {
        const int u0 = (k == 0) ? 0 : ((k - 1 + r) % 19) + 1;
        const int v0 = ((18 - k + r) % 19) + 1;
        const int pk = u0 < v0 ? u0 : v0;
        const int qk = u0 < v0 ? v0 : u0;
        const float ck = __shfl_sync(FULL, c, pk);
        const float sk = __shfl_sync(FULL, s, pk);
        const float ap = a[pk], aq = a[qk];
        a[pk] = fmaf(-sk, aq, ck * ap);
        a[qk] = fmaf( sk, ap, ck * aq);
        const float up = u[pk], uq = u[qk];
        u[pk] = fmaf(-sk, uq, ck * up);
        u[qk] = fmaf( sk, up, ck * uq);
      }

      m = (m == 0) ? 18 : m - 1;
    }
  }

  float lam = 0.f;
#pragma unroll
  for (int j = 0; j < 20; j++) lam = (lane == j) ? a[j] : lam;
  const float lg_own = __logf(fmaxf(lam, 1e-4f));

#pragma unroll
  for (int j = 0; j < 20; j++) {
    const float lgj = __shfl_sync(FULL, lg_own, j);
    if (lane < 20) {
      sW[warp][lane * 21 + j] = u[j] * lgj;
      sU[warp][lane * 21 + j] = u[j];
    }
  }
  __syncwarp();

  const float* Wm = sW[warp];
  const float* Um = sU[warp];
  float accv[10];
#pragma unroll
  for (int h = 0; h < 10; h++) accv[h] = 0.f;

  for (int t = lane; t < 210; t += 32) {
    int i = (int)((41.0f - sqrtf(fmaf(-8.f, (float)t, 1681.0f))) * 0.5f);
    int st = 20 * i - ((i * (i - 1)) >> 1);
    if (st > t) { i--; st = 20 * i - ((i * (i - 1)) >> 1); }
    else if (t >= st + (20 - i)) { st += 20 - i; i++; }
    const int k = i + (t - st);
    float mm = 0.f;
#pragma unroll
    for (int j = 0; j < 20; j++)
      mm = fmaf(Wm[i * 21 + j], Um[k * 21 + j], mm);
#pragma unroll
    for (int h = 0; h < 10; h++)
      accv[h] = fmaf(mm, lin_w[h * 210 + t], accv[h]);
  }
#pragma unroll
  for (int h = 0; h < 10; h++) {
    float v = accv[h];
    v += __shfl_xor_sync(FULL, v, 16);
    v += __shfl_xor_sync(FULL, v, 8);
    v += __shfl_xor_sync(FULL, v, 4);
    v += __shfl_xor_sync(FULL, v, 2);
    v += __shfl_xor_sync(FULL, v, 1);
    accv[h] = v;
  }
  if (lane == 0) {
#pragma unroll
    for (int h = 0; h < 10; h++) out[b * 10 + h] = accv[h] + lin_b[h];
  }
}

// ---------------------------------------------------------------------------
extern "C" void kernel_launch(void* const* d_in, const int* in_sizes, int n_in,
                              void* d_out, int out_size) {
  const float* x  = (const float*)d_in[0];
  const float* W  = (const float*)d_in[1];
  const float* lw = (const float*)d_in[2];
  const float* lb = (const float*)d_in[3];
  float* out = (float*)d_out;

  cudaFuncSetAttribute(gram_kernel, cudaFuncAttributeMaxDynamicSharedMemorySize,
                       94720);

  gram_kernel<<<4096, 256, 94720>>>(x, W);
  eig_kernel<<<1024, 128>>>(lw, lb, out);
}

// round 9
// speedup vs baseline: 2.7671x; 1.1052x over previous
#include <cuda_runtime.h>
#include <cuda_bf16.h>
#include <cstdint>
#include <math.h>

#define NSWEEP 5
#define FULL 0xffffffffu

// scratch: Y matrices (4096 x 20 x 20)
__device__ float g_Y[4096 * 400];

// ---------------------------------------------------------------------------
// helpers
// ---------------------------------------------------------------------------
__device__ __forceinline__ uint32_t s2u(const void* p) {
  return (uint32_t)__cvta_generic_to_shared(p);
}

__device__ __forceinline__ void ldsm4(uint32_t addr, uint32_t* r) {
  asm volatile("ldmatrix.sync.aligned.m8n8.x4.shared.b16 {%0,%1,%2,%3}, [%4];"
               : "=r"(r[0]), "=r"(r[1]), "=r"(r[2]), "=r"(r[3]) : "r"(addr));
}
__device__ __forceinline__ void mma16816(float* d, const uint32_t* a,
                                         uint32_t b0, uint32_t b1) {
  asm volatile(
      "mma.sync.aligned.m16n8k16.row.col.f32.bf16.bf16.f32 "
      "{%0,%1,%2,%3},{%4,%5,%6,%7},{%8,%9},{%0,%1,%2,%3};"
      : "+f"(d[0]), "+f"(d[1]), "+f"(d[2]), "+f"(d[3])
      : "r"(a[0]), "r"(a[1]), "r"(a[2]), "r"(a[3]), "r"(b0), "r"(b1));
}
__device__ __forceinline__ void bsplit(float v, __nv_bfloat16& h, __nv_bfloat16& l) {
  h = __float2bfloat16(v);
  l = __float2bfloat16(v - __bfloat162float(h));
}

// smem byte layout (total 93696):
//  [0,33792)      Xh 64x264 bf16      -> later Kh 64x72 @0, Kl @9216
//  [33792,67584)  Xl 64x264 bf16      -> later Pth 32x72 @33792, Ptl @38400
//  [67584,84224)  KK 64x65 f32
//  [84224,88832)  Wth 32x72 bf16
//  [88832,93440)  Wtl 32x72 bf16
//  [93440,93696)  sq 64 f32
#define OFF_XL  33792
#define OFF_KK  67584
#define OFF_WTH 84224
#define OFF_WTL 88832
#define OFF_SQ  93440
#define SMEM_BYTES 93696

// ---------------------------------------------------------------------------
// Kernel A: centering + tensor-core Gram + exp + tensor-core P=KW, Y=W^T P
// grid 4096, block 256
// ---------------------------------------------------------------------------
__global__ __launch_bounds__(256) void gram_kernel(const float* __restrict__ x,
                                                   const float* __restrict__ W) {
  extern __shared__ char smc[];
  __nv_bfloat16* Xh = (__nv_bfloat16*)smc;              // 64 x 264
  __nv_bfloat16* Xl = (__nv_bfloat16*)(smc + OFF_XL);   // 64 x 264
  float* KK  = (float*)(smc + OFF_KK);                  // 64 x 65
  __nv_bfloat16* Wth = (__nv_bfloat16*)(smc + OFF_WTH); // 32 x 72 (rows 20-31 unused)
  __nv_bfloat16* Wtl = (__nv_bfloat16*)(smc + OFF_WTL);
  float* sq  = (float*)(smc + OFF_SQ);                  // 64
  // overlays (valid after their region is dead):
  __nv_bfloat16* Kh  = (__nv_bfloat16*)smc;             // 64 x 72
  __nv_bfloat16* Kl  = (__nv_bfloat16*)(smc + 9216);    // 64 x 72
  __nv_bfloat16* Pth = (__nv_bfloat16*)(smc + OFF_XL);          // 32 x 72
  __nv_bfloat16* Ptl = (__nv_bfloat16*)(smc + OFF_XL + 4608);   // 32 x 72

  const int b    = blockIdx.x;
  const int tid  = threadIdx.x;
  const int warp = tid >> 5;
  const int lane = tid & 31;

  // ---- build Wt (transposed W, bf16 hi/lo) from global ----
  for (int i = tid; i < 20 * 64; i += 256) {
    const int d = i >> 6, k = i & 63;
    const float w = W[k * 20 + d];
    __nv_bfloat16 h, l;
    bsplit(w, h, l);
    Wth[d * 72 + k] = h;
    Wtl[d * 72 + k] = l;
  }

  // ---- load x[b], center, split into bf16 hi/lo ----
  const float* xb = x + (size_t)b * (64 * 256);
#pragma unroll
  for (int r8 = 0; r8 < 8; r8++) {
    const int r = warp * 8 + r8;
    const float4* row = (const float4*)(xb + r * 256);
    float4 v0 = row[lane];
    float4 v1 = row[lane + 32];
    float s = v0.x + v0.y + v0.z + v0.w + v1.x + v1.y + v1.z + v1.w;
    s += __shfl_xor_sync(FULL, s, 16);
    s += __shfl_xor_sync(FULL, s, 8);
    s += __shfl_xor_sync(FULL, s, 4);
    s += __shfl_xor_sync(FULL, s, 2);
    s += __shfl_xor_sync(FULL, s, 1);
    const float m = s * (1.0f / 256.0f);
    v0.x -= m; v0.y -= m; v0.z -= m; v0.w -= m;
    v1.x -= m; v1.y -= m; v1.z -= m; v1.w -= m;

    __nv_bfloat162* ph0 = (__nv_bfloat162*)(Xh + r * 264 + 4 * lane);
    __nv_bfloat162* pl0 = (__nv_bfloat162*)(Xl + r * 264 + 4 * lane);
    __nv_bfloat162* ph1 = (__nv_bfloat162*)(Xh + r * 264 + 128 + 4 * lane);
    __nv_bfloat162* pl1 = (__nv_bfloat162*)(Xl + r * 264 + 128 + 4 * lane);

    __nv_bfloat16 h, l;
    __nv_bfloat162 hh, ll;
    bsplit(v0.x, h, l); hh.x = h; ll.x = l;
    bsplit(v0.y, h, l); hh.y = h; ll.y = l;
    ph0[0] = hh; pl0[0] = ll;
    bsplit(v0.z, h, l); hh.x = h; ll.x = l;
    bsplit(v0.w, h, l); hh.y = h; ll.y = l;
    ph0[1] = hh; pl0[1] = ll;
    bsplit(v1.x, h, l); hh.x = h; ll.x = l;
    bsplit(v1.y, h, l); hh.y = h; ll.y = l;
    ph1[0] = hh; pl1[0] = ll;
    bsplit(v1.z, h, l); hh.x = h; ll.x = l;
    bsplit(v1.w, h, l); hh.y = h; ll.y = l;
    ph1[1] = hh; pl1[1] = ll;
  }
  __syncthreads();

  // fragment geometry shared by all MMA phases
  const int mrow = lane & 7;
  const int msel = lane >> 3;
  const int cofs = (msel >> 1) * 8;
  const int rsel = (msel & 1) * 8;
  const int r0 = lane >> 2;
  const int cb = 2 * (lane & 3);

  // ---- Gram via mma: warp handles blocks (bi,bj) and (bi+32,bj) ----
  {
    const int bj = (warp & 3) * 16;
    const int bi = (warp >> 2) * 16;
    const uint32_t LOFF = 64 * 264 * 2;  // bytes Xh -> Xl

    uint32_t aA0 = s2u(Xh + (bi + rsel + mrow) * 264 + cofs);
    uint32_t aA1 = aA0 + 32 * 264 * 2;
    uint32_t aB  = s2u(Xh + (bj + rsel + mrow) * 264 + cofs);

    float c0[8], c1[8];
#pragma unroll
    for (int i = 0; i < 8; i++) { c0[i] = 0.f; c1[i] = 0.f; }

#pragma unroll 4
    for (int kc = 0; kc < 16; kc++) {
      uint32_t Ah[4], Al[4], Bh[4], Bl[4], A1h[4], A1l[4];
      ldsm4(aA0, Ah);  ldsm4(aA0 + LOFF, Al);
      ldsm4(aA1, A1h); ldsm4(aA1 + LOFF, A1l);
      ldsm4(aB, Bh);   ldsm4(aB + LOFF, Bl);

      mma16816(c0,     Ah,  Bh[0], Bh[2]);
      mma16816(c0,     Ah,  Bl[0], Bl[2]);
      mma16816(c0,     Al,  Bh[0], Bh[2]);
      mma16816(c0 + 4, Ah,  Bh[1], Bh[3]);
      mma16816(c0 + 4, Ah,  Bl[1], Bl[3]);
      mma16816(c0 + 4, Al,  Bh[1], Bh[3]);

      mma16816(c1,     A1h, Bh[0], Bh[2]);
      mma16816(c1,     A1h, Bl[0], Bl[2]);
      mma16816(c1,     A1l, Bh[0], Bh[2]);
      mma16816(c1 + 4, A1h, Bh[1], Bh[3]);
      mma16816(c1 + 4, A1h, Bl[1], Bl[3]);
      mma16816(c1 + 4, A1l, Bh[1], Bh[3]);

      aA0 += 32; aA1 += 32; aB += 32;
    }

    float* K0 = KK + (bi + r0) * 65 + bj + cb;
    K0[0] = c0[0];  K0[1] = c0[1];
    K0[8 * 65] = c0[2];  K0[8 * 65 + 1] = c0[3];
    K0[8] = c0[4];  K0[9] = c0[5];
    K0[8 * 65 + 8] = c0[6];  K0[8 * 65 + 9] = c0[7];
    float* K1 = KK + (bi + 32 + r0) * 65 + bj + cb;
    K1[0] = c1[0];  K1[1] = c1[1];
    K1[8 * 65] = c1[2];  K1[8 * 65 + 1] = c1[3];
    K1[8] = c1[4];  K1[9] = c1[5];
    K1[8 * 65 + 8] = c1[6];  K1[8 * 65 + 9] = c1[7];
  }
  __syncthreads();

  if (tid < 64) sq[tid] = KK[tid * 65 + tid];
  __syncthreads();

  // ---- K = exp(-50 * d2) -> bf16 hi/lo into Kh/Kl (overlay on dead Xh) ----
  for (int e = tid; e < 4096; e += 256) {
    const int c = e >> 6, d = e & 63;
    const float g = KK[c * 65 + d];
    float d2 = sq[c] + sq[d] - 2.f * g;
    d2 = fmaxf(d2, 0.f) * (1.0f / 256.0f);
    const float kv = __expf(-50.f * d2);
    __nv_bfloat16 h, l;
    bsplit(kv, h, l);
    Kh[c * 72 + d] = h;
    Kl[c * 72 + d] = l;
  }
  __syncthreads();

  // ---- P = K * W via mma -> Pt (transposed, bf16 hi/lo, overlay dead Xl) ----
  {
    const int bi = (warp & 3) * 16;       // c tile (rows of K)
    const int nh = (warp >> 2) * 16;      // d half (cols 0-15 / 16-31)

    uint32_t aA = s2u(Kh + (bi + rsel + mrow) * 72 + cofs);
    uint32_t aB = s2u(Wth + (nh + rsel + mrow) * 72 + cofs);
    const uint32_t KLO = 9216;   // Kh->Kl bytes
    const uint32_t WLO = 4608;   // Wth->Wtl bytes

    float c0[8];
#pragma unroll
    for (int i = 0; i < 8; i++) c0[i] = 0.f;

#pragma unroll
    for (int kc = 0; kc < 4; kc++) {
      uint32_t Ah[4], Al[4], Bh[4], Bl[4];
      ldsm4(aA, Ah); ldsm4(aA + KLO, Al);
      ldsm4(aB, Bh); ldsm4(aB + WLO, Bl);
      mma16816(c0,     Ah, Bh[0], Bh[2]);
      mma16816(c0,     Ah, Bl[0], Bl[2]);
      mma16816(c0,     Al, Bh[0], Bh[2]);
      mma16816(c0 + 4, Ah, Bh[1], Bh[3]);
      mma16816(c0 + 4, Ah, Bl[1], Bl[3]);
      mma16816(c0 + 4, Al, Bh[1], Bh[3]);
      aA += 32; aB += 32;
    }

    // store transposed + split: Pt[d][c]
    const int cc0 = bi + r0;          // c of regs 0,1,4,5
    const int cc1 = bi + r0 + 8;      // c of regs 2,3,6,7
    const int dd0 = nh + cb;          // d of regs 0,2
    __nv_bfloat16 h, l;
#pragma unroll
    for (int i = 0; i < 8; i++) {
      const int dd = dd0 + (i & 1) + ((i >> 2) << 3);   // +1 for odd, +8 for i>=4
      const int cc = (i & 2) ? cc1 : cc0;
      bsplit(c0[i], h, l);
      Pth[dd * 72 + cc] = h;
      Ptl[dd * 72 + cc] = l;
    }
  }
  __syncthreads();

  // ---- Y = W^T * P via mma (warps 0-3) -> g_Y ----
  if (warp < 4) {
    const int e0 = (warp & 1) * 16;
    const int f0 = (warp >> 1) * 16;

    uint32_t aA = s2u(Wth + (e0 + rsel + mrow) * 72 + cofs);
    uint32_t aB = s2u(Pth + (f0 + rsel + mrow) * 72 + cofs);
    const uint32_t WLO = 4608;
    const uint32_t PLO = 4608;

    float c0[8];
#pragma unroll
    for (int i = 0; i < 8; i++) c0[i] = 0.f;

#pragma unroll
    for (int kc = 0; kc < 4; kc++) {
      uint32_t Ah[4], Al[4], Bh[4], Bl[4];
      ldsm4(aA, Ah); ldsm4(aA + WLO, Al);
      ldsm4(aB, Bh); ldsm4(aB + PLO, Bl);
      mma16816(c0,     Ah, Bh[0], Bh[2]);
      mma16816(c0,     Ah, Bl[0], Bl[2]);
      mma16816(c0,     Al, Bh[0], Bh[2]);
      mma16816(c0 + 4, Ah, Bh[1], Bh[3]);
      mma16816(c0 + 4, Ah, Bl[1], Bl[3]);
      mma16816(c0 + 4, Al, Bh[1], Bh[3]);
      aA += 32; aB += 32;
    }

    float* Yb = g_Y + (size_t)b * 400;
#pragma unroll
    for (int i = 0; i < 8; i++) {
      const int ee = e0 + r0 + ((i & 2) ? 8 : 0);
      const int ff = f0 + cb + (i & 1) + ((i >> 2) << 3);
      if (ee < 20 && ff < 20) Yb[ee * 20 + ff] = c0[i];
    }
  }
}

// ---------------------------------------------------------------------------
// Kernel B: register-resident warp Jacobi, local angles, incremental schedule.
// ---------------------------------------------------------------------------
__global__ __launch_bounds__(128, 4) void eig_kernel(const float* __restrict__ lin_w,
                                                     const float* __restrict__ lin_b,
                                                     float* __restrict__ out) {
  __shared__ float sW[4][420];
  __shared__ float sU[4][420];

  const int warp = threadIdx.x >> 5;
  const int lane = threadIdx.x & 31;
  const int b = blockIdx.x * 4 + warp;
  const float* Yb = g_Y + (size_t)b * 400;

  float a[20], u[20];
#pragma unroll
  for (int j = 0; j < 20; j++) {
    a[j] = (lane < 20) ? Yb[lane * 20 + j] : 0.f;
    u[j] = (lane == j) ? 1.f : 0.f;
  }
  float dg = (lane < 20) ? Yb[lane * 20 + lane] : 0.f;

  int m = (lane + 37) % 19;

  for (int sw = 0; sw < NSWEEP; sw++) {
#pragma unroll
    for (int r = 0; r < 19; r++) {
      const int C = (2 * r + 18) % 19;
      const int D = ((18 + r) % 19) + 1;
      int uu = C - lane;
      uu += (uu < 0) ? 19 : 0;
      uu += (uu < 0) ? 19 : 0;
      int t = (m == 18) ? 0 : uu + 1;
      t = (lane == 0) ? D : t;
      const bool isp = lane < t;

      float s0 = 0.f, s1 = 0.f, s2 = 0.f, s3 = 0.f;
#pragma unroll
      for (int j = 0; j < 5; j++)  s0 = (t == j)      ? a[j]      : s0;
#pragma unroll
      for (int j = 0; j < 5; j++)  s1 = (t == j + 5)  ? a[j + 5]  : s1;
#pragma unroll
      for (int j = 0; j < 5; j++)  s2 = (t == j + 10) ? a[j + 10] : s2;
#pragma unroll
      for (int j = 0; j < 5; j++)  s3 = (t == j + 15) ? a[j + 15] : s3;
      const float apq_own = (s0 + s1) + (s2 + s3);

      const float att = __shfl_sync(FULL, dg, t);
      const float apq = 0.5f * (apq_own + __shfl_sync(FULL, apq_own, t));

      const float app = isp ? dg : att;
      const float aqq = isp ? att : dg;
      float c, s, tg;
      {
        const float tau = (aqq - app) * (0.5f / apq);
        const float tt  = copysignf(1.f, tau) / (fabsf(tau) + sqrtf(fmaf(tau, tau, 1.f)));
        const float cc  = rsqrtf(fmaf(tt, tt, 1.f));
        const float ss  = tt * cc;
        const bool ok = (fabsf(apq) > 1e-20f) && (lane < 20);
        c  = ok ? cc : 1.f;
        s  = ok ? ss : 0.f;
        tg = ok ? tt : 0.f;
      }

      dg = fmaf(isp ? -tg : tg, apq, dg);

      {
        const float se = isp ? -s : s;
#pragma unroll
        for (int j = 0; j < 20; j++) {
          const float rt = __shfl_sync(FULL, a[j], t);
          a[j] = fmaf(se, rt, c * a[j]);
        }
      }

#pragma unroll
      for (int k = 0; k < 10; k++) {
        const int u0 = (k == 0) ? 0 : ((k - 1 + r) % 19) + 1;
        const int v0 = ((18 - k + r) % 19) + 1;
        const int pk = u0 < v0 ? u0 : v0;
        const int qk = u0 < v0 ? v0 : u0;
        const float ck = __shfl_sync(FULL, c, pk);
        const float sk = __shfl_sync(FULL, s, pk);
        const float ap = a[pk], aq = a[qk];
        a[pk] = fmaf(-sk, aq, ck * ap);
        a[qk] = fmaf( sk, ap, ck * aq);
        const float up = u[pk], uq = u[qk];
        u[pk] = fmaf(-sk, uq, ck * up);
        u[qk] = fmaf( sk, up, ck * uq);
      }

      m = (m == 0) ? 18 : m - 1;
    }
  }

  float lam = 0.f;
#pragma unroll
  for (int j = 0; j < 20; j++) lam = (lane == j) ? a[j] : lam;
  const float lg_own = __logf(fmaxf(lam, 1e-4f));

#pragma unroll
  for (int j = 0; j < 20; j++) {
    const float lgj = __shfl_sync(FULL, lg_own, j);
    if (lane < 20) {
      sW[warp][lane * 21 + j] = u[j] * lgj;
      sU[warp][lane * 21 + j] = u[j];
    }
  }
  __syncwarp();

  const float* Wm = sW[warp];
  const float* Um = sU[warp];
  float accv[10];
#pragma unroll
  for (int h = 0; h < 10; h++) accv[h] = 0.f;

  for (int t = lane; t < 210; t += 32) {
    int i = (int)((41.0f - sqrtf(fmaf(-8.f, (float)t, 1681.0f))) * 0.5f);
    int st = 20 * i - ((i * (i - 1)) >> 1);
    if (st > t) { i--; st = 20 * i - ((i * (i - 1)) >> 1); }
    else if (t >= st + (20 - i)) { st += 20 - i; i++; }
    const int k = i + (t - st);
    float mm = 0.f;
#pragma unroll
    for (int j = 0; j < 20; j++)
      mm = fmaf(Wm[i * 21 + j], Um[k * 21 + j], mm);
#pragma unroll
    for (int h = 0; h < 10; h++)
      accv[h] = fmaf(mm, lin_w[h * 210 + t], accv[h]);
  }
#pragma unroll
  for (int h = 0; h < 10; h++) {
    float v = accv[h];
    v += __shfl_xor_sync(FULL, v, 16);
    v += __shfl_xor_sync(FULL, v, 8);
    v += __shfl_xor_sync(FULL, v, 4);
    v += __shfl_xor_sync(FULL, v, 2);
    v += __shfl_xor_sync(FULL, v, 1);
    accv[h] = v;
  }
  if (lane == 0) {
#pragma unroll
    for (int h = 0; h < 10; h++) out[b * 10 + h] = accv[h] + lin_b[h];
  }
}

// ---------------------------------------------------------------------------
extern "C" void kernel_launch(void* const* d_in, const int* in_sizes, int n_in,
                              void* d_out, int out_size) {
  const float* x  = (const float*)d_in[0];
  const float* W  = (const float*)d_in[1];
  const float* lw = (const float*)d_in[2];
  const float* lb = (const float*)d_in[3];
  float* out = (float*)d_out;

  cudaFuncSetAttribute(gram_kernel, cudaFuncAttributeMaxDynamicSharedMemorySize,
                       SMEM_BYTES);

  gram_kernel<<<4096, 256, SMEM_BYTES>>>(x, W);
  eig_kernel<<<1024, 128>>>(lw, lb, out);
}

// round 11
// speedup vs baseline: 2.9438x; 1.0639x over previous
#include <cuda_runtime.h>
#include <cuda_bf16.h>
#include <cstdint>
#include <math.h>

#define NSWEEP 5
#define FULL 0xffffffffu

typedef unsigned long long u64;

// scratch: Y matrices (4096 x 20 x 20)
__device__ float g_Y[4096 * 400];

// ---------------------------------------------------------------------------
// helpers
// ---------------------------------------------------------------------------
__device__ __forceinline__ uint32_t s2u(const void* p) {
  return (uint32_t)__cvta_generic_to_shared(p);
}

__device__ __forceinline__ void ldsm4(uint32_t addr, uint32_t* r) {
  asm volatile("ldmatrix.sync.aligned.m8n8.x4.shared.b16 {%0,%1,%2,%3}, [%4];"
               : "=r"(r[0]), "=r"(r[1]), "=r"(r[2]), "=r"(r[3]) : "r"(addr));
}
__device__ __forceinline__ void mma16816(float* d, const uint32_t* a,
                                         uint32_t b0, uint32_t b1) {
  asm volatile(
      "mma.sync.aligned.m16n8k16.row.col.f32.bf16.bf16.f32 "
      "{%0,%1,%2,%3},{%4,%5,%6,%7},{%8,%9},{%0,%1,%2,%3};"
      : "+f"(d[0]), "+f"(d[1]), "+f"(d[2]), "+f"(d[3])
      : "r"(a[0]), "r"(a[1]), "r"(a[2]), "r"(a[3]), "r"(b0), "r"(b1));
}
__device__ __forceinline__ void bsplit(float v, __nv_bfloat16& h, __nv_bfloat16& l) {
  h = __float2bfloat16(v);
  l = __float2bfloat16(v - __bfloat162float(h));
}

// ---- packed f32x2 helpers ----
__device__ __forceinline__ u64 pk2(float lo, float hi) {
  u64 r; asm("mov.b64 %0,{%1,%2};" : "=l"(r) : "f"(lo), "f"(hi)); return r;
}
__device__ __forceinline__ u64 bc2(float v) { return pk2(v, v); }
__device__ __forceinline__ void up2(u64 v, float& lo, float& hi) {
  asm("mov.b64 {%0,%1},%2;" : "=f"(lo), "=f"(hi) : "l"(v));
}
__device__ __forceinline__ u64 fma2(u64 a, u64 b, u64 c) {
  u64 d; asm("fma.rn.f32x2 %0,%1,%2,%3;" : "=l"(d) : "l"(a), "l"(b), "l"(c)); return d;
}
__device__ __forceinline__ u64 mul2(u64 a, u64 b) {
  u64 d; asm("mul.rn.f32x2 %0,%1,%2;" : "=l"(d) : "l"(a), "l"(b)); return d;
}
__device__ __forceinline__ u64 add2(u64 a, u64 b) {
  u64 d; asm("add.rn.f32x2 %0,%1,%2;" : "=l"(d) : "l"(a), "l"(b)); return d;
}
__device__ __forceinline__ u64 neg2(u64 a) { return a ^ 0x8000000080000000ULL; }

// smem byte layout (total 93696) for gram_kernel:
//  [0,33792)      Xh 64x264 bf16      -> later Kh 64x72 @0, Kl @9216
//  [33792,67584)  Xl 64x264 bf16      -> later Pth 32x72 @33792, Ptl @38400
//  [67584,84224)  KK 64x65 f32
//  [84224,88832)  Wth 32x72 bf16
//  [88832,93440)  Wtl 32x72 bf16
//  [93440,93696)  sq 64 f32
#define OFF_XL  33792
#define OFF_KK  67584
#define OFF_WTH 84224
#define OFF_WTL 88832
#define OFF_SQ  93440
#define SMEM_BYTES 93696

// ---------------------------------------------------------------------------
// Kernel A: centering + tensor-core Gram + exp + tensor-core P=KW, Y=W^T P
// (unchanged from round 9 — passing at ~143us)
// ---------------------------------------------------------------------------
__global__ __launch_bounds__(256) void gram_kernel(const float* __restrict__ x,
                                                   const float* __restrict__ W) {
  extern __shared__ char smc[];
  __nv_bfloat16* Xh = (__nv_bfloat16*)smc;              // 64 x 264
  __nv_bfloat16* Xl = (__nv_bfloat16*)(smc + OFF_XL);   // 64 x 264
  float* KK  = (float*)(smc + OFF_KK);                  // 64 x 65
  __nv_bfloat16* Wth = (__nv_bfloat16*)(smc + OFF_WTH); // 32 x 72
  __nv_bfloat16* Wtl = (__nv_bfloat16*)(smc + OFF_WTL);
  float* sq  = (float*)(smc + OFF_SQ);                  // 64
  __nv_bfloat16* Kh  = (__nv_bfloat16*)smc;             // 64 x 72
  __nv_bfloat16* Kl  = (__nv_bfloat16*)(smc + 9216);    // 64 x 72
  __nv_bfloat16* Pth = (__nv_bfloat16*)(smc + OFF_XL);          // 32 x 72
  __nv_bfloat16* Ptl = (__nv_bfloat16*)(smc + OFF_XL + 4608);   // 32 x 72

  const int b    = blockIdx.x;
  const int tid  = threadIdx.x;
  const int warp = tid >> 5;
  const int lane = tid & 31;

  for (int i = tid; i < 20 * 64; i += 256) {
    const int d = i >> 6, k = i & 63;
    const float w = W[k * 20 + d];
    __nv_bfloat16 h, l;
    bsplit(w, h, l);
    Wth[d * 72 + k] = h;
    Wtl[d * 72 + k] = l;
  }

  const float* xb = x + (size_t)b * (64 * 256);
#pragma unroll
  for (int r8 = 0; r8 < 8; r8++) {
    const int r = warp * 8 + r8;
    const float4* row = (const float4*)(xb + r * 256);
    float4 v0 = row[lane];
    float4 v1 = row[lane + 32];
    float s = v0.x + v0.y + v0.z + v0.w + v1.x + v1.y + v1.z + v1.w;
    s += __shfl_xor_sync(FULL, s, 16);
    s += __shfl_xor_sync(FULL, s, 8);
    s += __shfl_xor_sync(FULL, s, 4);
    s += __shfl_xor_sync(FULL, s, 2);
    s += __shfl_xor_sync(FULL, s, 1);
    const float m = s * (1.0f / 256.0f);
    v0.x -= m; v0.y -= m; v0.z -= m; v0.w -= m;
    v1.x -= m; v1.y -= m; v1.z -= m; v1.w -= m;

    __nv_bfloat162* ph0 = (__nv_bfloat162*)(Xh + r * 264 + 4 * lane);
    __nv_bfloat162* pl0 = (__nv_bfloat162*)(Xl + r * 264 + 4 * lane);
    __nv_bfloat162* ph1 = (__nv_bfloat162*)(Xh + r * 264 + 128 + 4 * lane);
    __nv_bfloat162* pl1 = (__nv_bfloat162*)(Xl + r * 264 + 128 + 4 * lane);

    __nv_bfloat16 h, l;
    __nv_bfloat162 hh, ll;
    bsplit(v0.x, h, l); hh.x = h; ll.x = l;
    bsplit(v0.y, h, l); hh.y = h; ll.y = l;
    ph0[0] = hh; pl0[0] = ll;
    bsplit(v0.z, h, l); hh.x = h; ll.x = l;
    bsplit(v0.w, h, l); hh.y = h; ll.y = l;
    ph0[1] = hh; pl0[1] = ll;
    bsplit(v1.x, h, l); hh.x = h; ll.x = l;
    bsplit(v1.y, h, l); hh.y = h; ll.y = l;
    ph1[0] = hh; pl1[0] = ll;
    bsplit(v1.z, h, l); hh.x = h; ll.x = l;
    bsplit(v1.w, h, l); hh.y = h; ll.y = l;
    ph1[1] = hh; pl1[1] = ll;
  }
  __syncthreads();

  const int mrow = lane & 7;
  const int msel = lane >> 3;
  const int cofs = (msel >> 1) * 8;
  const int rsel = (msel & 1) * 8;
  const int r0 = lane >> 2;
  const int cb = 2 * (lane & 3);

  {
    const int bj = (warp & 3) * 16;
    const int bi = (warp >> 2) * 16;
    const uint32_t LOFF = 64 * 264 * 2;

    uint32_t aA0 = s2u(Xh + (bi + rsel + mrow) * 264 + cofs);
    uint32_t aA1 = aA0 + 32 * 264 * 2;
    uint32_t aB  = s2u(Xh + (bj + rsel + mrow) * 264 + cofs);

    float c0[8], c1[8];
#pragma unroll
    for (int i = 0; i < 8; i++) { c0[i] = 0.f; c1[i] = 0.f; }

#pragma unroll 4
    for (int kc = 0; kc < 16; kc++) {
      uint32_t Ah[4], Al[4], Bh[4], Bl[4], A1h[4], A1l[4];
      ldsm4(aA0, Ah);  ldsm4(aA0 + LOFF, Al);
      ldsm4(aA1, A1h); ldsm4(aA1 + LOFF, A1l);
      ldsm4(aB, Bh);   ldsm4(aB + LOFF, Bl);

      mma16816(c0,     Ah,  Bh[0], Bh[2]);
      mma16816(c0,     Ah,  Bl[0], Bl[2]);
      mma16816(c0,     Al,  Bh[0], Bh[2]);
      mma16816(c0 + 4, Ah,  Bh[1], Bh[3]);
      mma16816(c0 + 4, Ah,  Bl[1], Bl[3]);
      mma16816(c0 + 4, Al,  Bh[1], Bh[3]);

      mma16816(c1,     A1h, Bh[0], Bh[2]);
      mma16816(c1,     A1h, Bl[0], Bl[2]);
      mma16816(c1,     A1l, Bh[0], Bh[2]);
      mma16816(c1 + 4, A1h, Bh[1], Bh[3]);
      mma16816(c1 + 4, A1h, Bl[1], Bl[3]);
      mma16816(c1 + 4, A1l, Bh[1], Bh[3]);

      aA0 += 32; aA1 += 32; aB += 32;
    }

    float* K0 = KK + (bi + r0) * 65 + bj + cb;
    K0[0] = c0[0];  K0[1] = c0[1];
    K0[8 * 65] = c0[2];  K0[8 * 65 + 1] = c0[3];
    K0[8] = c0[4];  K0[9] = c0[5];
    K0[8 * 65 + 8] = c0[6];  K0[8 * 65 + 9] = c0[7];
    float* K1 = KK + (bi + 32 + r0) * 65 + bj + cb;
    K1[0] = c1[0];  K1[1] = c1[1];
    K1[8 * 65] = c1[2];  K1[8 * 65 + 1] = c1[3];
    K1[8] = c1[4];  K1[9] = c1[5];
    K1[8 * 65 + 8] = c1[6];  K1[8 * 65 + 9] = c1[7];
  }
  __syncthreads();

  if (tid < 64) sq[tid] = KK[tid * 65 + tid];
  __syncthreads();

  for (int e = tid; e < 4096; e += 256) {
    const int c = e >> 6, d = e & 63;
    const float g = KK[c * 65 + d];
    float d2 = sq[c] + sq[d] - 2.f * g;
    d2 = fmaxf(d2, 0.f) * (1.0f / 256.0f);
    const float kv = __expf(-50.f * d2);
    __nv_bfloat16 h, l;
    bsplit(kv, h, l);
    Kh[c * 72 + d] = h;
    Kl[c * 72 + d] = l;
  }
  __syncthreads();

  {
    const int bi = (warp & 3) * 16;
    const int nh = (warp >> 2) * 16;

    uint32_t aA = s2u(Kh + (bi + rsel + mrow) * 72 + cofs);
    uint32_t aB = s2u(Wth + (nh + rsel + mrow) * 72 + cofs);
    const uint32_t KLO = 9216;
    const uint32_t WLO = 4608;

    float c0[8];
#pragma unroll
    for (int i = 0; i < 8; i++) c0[i] = 0.f;

#pragma unroll
    for (int kc = 0; kc < 4; kc++) {
      uint32_t Ah[4], Al[4], Bh[4], Bl[4];
      ldsm4(aA, Ah); ldsm4(aA + KLO, Al);
      ldsm4(aB, Bh); ldsm4(aB + WLO, Bl);
      mma16816(c0,     Ah, Bh[0], Bh[2]);
      mma16816(c0,     Ah, Bl[0], Bl[2]);
      mma16816(c0,     Al, Bh[0], Bh[2]);
      mma16816(c0 + 4, Ah, Bh[1], Bh[3]);
      mma16816(c0 + 4, Ah, Bl[1], Bl[3]);
      mma16816(c0 + 4, Al, Bh[1], Bh[3]);
      aA += 32; aB += 32;
    }

    const int cc0 = bi + r0;
    const int cc1 = bi + r0 + 8;
    const int dd0 = nh + cb;
    __nv_bfloat16 h, l;
#pragma unroll
    for (int i = 0; i < 8; i++) {
      const int dd = dd0 + (i & 1) + ((i >> 2) << 3);
      const int cc = (i & 2) ? cc1 : cc0;
      bsplit(c0[i], h, l);
      Pth[dd * 72 + cc] = h;
      Ptl[dd * 72 + cc] = l;
    }
  }
  __syncthreads();

  if (warp < 4) {
    const int e0 = (warp & 1) * 16;
    const int f0 = (warp >> 1) * 16;

    uint32_t aA = s2u(Wth + (e0 + rsel + mrow) * 72 + cofs);
    uint32_t aB = s2u(Pth + (f0 + rsel + mrow) * 72 + cofs);
    const uint32_t WLO = 4608;
    const uint32_t PLO = 4608;

    float c0[8];
#pragma unroll
    for (int i = 0; i < 8; i++) c0[i] = 0.f;

#pragma unroll
    for (int kc = 0; kc < 4; kc++) {
      uint32_t Ah[4], Al[4], Bh[4], Bl[4];
      ldsm4(aA, Ah); ldsm4(aA + WLO, Al);
      ldsm4(aB, Bh); ldsm4(aB + PLO, Bl);
      mma16816(c0,     Ah, Bh[0], Bh[2]);
      mma16816(c0,     Ah, Bl[0], Bl[2]);
      mma16816(c0,     Al, Bh[0], Bh[2]);
      mma16816(c0 + 4, Ah, Bh[1], Bh[3]);
      mma16816(c0 + 4, Ah, Bl[1], Bl[3]);
      mma16816(c0 + 4, Al, Bh[1], Bh[3]);
      aA += 32; aB += 32;
    }

    float* Yb = g_Y + (size_t)b * 400;
#pragma unroll
    for (int i = 0; i < 8; i++) {
      const int ee = e0 + r0 + ((i & 2) ? 8 : 0);
      const int ff = f0 + cb + (i & 1) + ((i >> 2) << 3);
      if (ee < 20 && ff < 20) Yb[ee * 20 + ff] = c0[i];
    }
  }
}

// ---------------------------------------------------------------------------
// Kernel B: packed-f32x2 warp Jacobi — TWO matrices per warp (lo/hi halves).
// grid 512, block 128 (4 warps => 8 matrices per block). Single wave.
// ---------------------------------------------------------------------------
__global__ __launch_bounds__(128, 4) void eig_kernel(const float* __restrict__ lin_w,
                                                     const float* __restrict__ lin_b,
                                                     float* __restrict__ out) {
  __shared__ u64 sW[4][420];   // packed U*diag(logS), 20x21, per warp
  __shared__ u64 sU[4][420];   // packed U

  const int warp = threadIdx.x >> 5;
  const int lane = threadIdx.x & 31;
  const int b0 = (blockIdx.x * 4 + warp) * 2;
  const float* Y0 = g_Y + (size_t)b0 * 400;
  const float* Y1 = Y0 + 400;

  u64 a[20], u[20];
#pragma unroll
  for (int j = 0; j < 20; j++) {
    a[j] = (lane < 20) ? pk2(Y0[lane * 20 + j], Y1[lane * 20 + j]) : 0ULL;
    u[j] = (lane == j) ? bc2(1.f) : 0ULL;
  }
  u64 dg = (lane < 20) ? pk2(Y0[lane * 21], Y1[lane * 21]) : 0ULL;  // [lane*20+lane]

  int m = (lane + 37) % 19;

  for (int sw = 0; sw < NSWEEP; sw++) {
#pragma unroll
    for (int r = 0; r < 19; r++) {
      const int C = (2 * r + 18) % 19;
      const int D = ((18 + r) % 19) + 1;
      int uu = C - lane;
      uu += (uu < 0) ? 19 : 0;
      uu += (uu < 0) ? 19 : 0;
      int t = (m == 18) ? 0 : uu + 1;
      t = (lane == 0) ? D : t;
      const bool isp = lane < t;

      // ---- apq = A[lane][t] via select tree on packed regs ----
      u64 s0 = 0ULL, s1 = 0ULL, s2 = 0ULL, s3 = 0ULL;
#pragma unroll
      for (int j = 0; j < 5; j++)  s0 = (t == j)      ? a[j]      : s0;
#pragma unroll
      for (int j = 0; j < 5; j++)  s1 = (t == j + 5)  ? a[j + 5]  : s1;
#pragma unroll
      for (int j = 0; j < 5; j++)  s2 = (t == j + 10) ? a[j + 10] : s2;
#pragma unroll
      for (int j = 0; j < 5; j++)  s3 = (t == j + 15) ? a[j + 15] : s3;
      const u64 apq_own = add2(add2(s0, s1), add2(s2, s3));

      const u64 att = __shfl_sync(FULL, dg, t);
      const u64 apq = mul2(bc2(0.5f), add2(apq_own, __shfl_sync(FULL, apq_own, t)));

      // ---- angles, scalar per matrix (identical on both pair lanes) ----
      float apqx, apqy, dgx, dgy, atx, aty;
      up2(apq, apqx, apqy);
      up2(dg, dgx, dgy);
      up2(att, atx, aty);
      float cx, sx, tgx, cy, sy, tgy;
      {
        const float app = isp ? dgx : atx;
        const float aqq = isp ? atx : dgx;
        const float tau = (aqq - app) * (0.5f / apqx);
        const float tt  = copysignf(1.f, tau) / (fabsf(tau) + sqrtf(fmaf(tau, tau, 1.f)));
        const float cc  = rsqrtf(fmaf(tt, tt, 1.f));
        const bool ok = (fabsf(apqx) > 1e-20f) && (lane < 20);
        cx  = ok ? cc : 1.f;
        sx  = ok ? tt * cc : 0.f;
        tgx = ok ? tt : 0.f;
      }
      {
        const float app = isp ? dgy : aty;
        const float aqq = isp ? aty : dgy;
        const float tau = (aqq - app) * (0.5f / apqy);
        const float tt  = copysignf(1.f, tau) / (fabsf(tau) + sqrtf(fmaf(tau, tau, 1.f)));
        const float cc  = rsqrtf(fmaf(tt, tt, 1.f));
        const bool ok = (fabsf(apqy) > 1e-20f) && (lane < 20);
        cy  = ok ? cc : 1.f;
        sy  = ok ? tt * cc : 0.f;
        tgy = ok ? tt : 0.f;
      }
      const u64 c  = pk2(cx, cy);
      const u64 s  = pk2(sx, sy);
      const u64 tg = pk2(tgx, tgy);

      // ---- exact diagonal update ----
      dg = fma2(isp ? neg2(tg) : tg, apq, dg);

      // ---- row phase ----
      {
        const u64 se = isp ? neg2(s) : s;
#pragma unroll
        for (int j = 0; j < 20; j++) {
          const u64 rt = __shfl_sync(FULL, a[j], t);
          a[j] = fma2(se, rt, mul2(c, a[j]));
        }
      }

      // ---- col phase ----
#pragma unroll
      for (int k = 0; k < 10; k++) {
        const int u0 = (k == 0) ? 0 : ((k - 1 + r) % 19) + 1;
        const int v0 = ((18 - k + r) % 19) + 1;
        const int pk = u0 < v0 ? u0 : v0;
        const int qk = u0 < v0 ? v0 : u0;
        const u64 ck  = __shfl_sync(FULL, c, pk);
        const u64 sk  = __shfl_sync(FULL, s, pk);
        const u64 nsk = neg2(sk);
        const u64 ap = a[pk], aq = a[qk];
        a[pk] = fma2(nsk, aq, mul2(ck, ap));
        a[qk] = fma2(sk,  ap, mul2(ck, aq));
        const u64 up = u[pk], uq = u[qk];
        u[pk] = fma2(nsk, uq, mul2(ck, up));
        u[qk] = fma2(sk,  up, mul2(ck, uq));
      }

      m = (m == 0) ? 18 : m - 1;
    }
  }

  // ---- eigenvalues from converged diagonal of a[] ----
  u64 lam = 0ULL;
#pragma unroll
  for (int j = 0; j < 20; j++) lam = (lane == j) ? a[j] : lam;
  float lamx, lamy;
  up2(lam, lamx, lamy);
  const u64 lg_pk = pk2(__logf(fmaxf(lamx, 1e-4f)), __logf(fmaxf(lamy, 1e-4f)));

  // ---- W = U*diag(logS), U -> smem (packed) ----
#pragma unroll
  for (int j = 0; j < 20; j++) {
    const u64 lgj = __shfl_sync(FULL, lg_pk, j);
    if (lane < 20) {
      sW[warp][lane * 21 + j] = mul2(u[j], lgj);
      sU[warp][lane * 21 + j] = u[j];
    }
  }
  __syncwarp();

  // ---- triu(M) fused with linear head (packed) ----
  const u64* Wm = sW[warp];
  const u64* Um = sU[warp];
  u64 accv[10];
#pragma unroll
  for (int h = 0; h < 10; h++) accv[h] = 0ULL;

  for (int t = lane; t < 210; t += 32) {
    int i = (int)((41.0f - sqrtf(fmaf(-8.f, (float)t, 1681.0f))) * 0.5f);
    int st = 20 * i - ((i * (i - 1)) >> 1);
    if (st > t) { i--; st = 20 * i - ((i * (i - 1)) >> 1); }
    else if (t >= st + (20 - i)) { st += 20 - i; i++; }
    const int k = i + (t - st);
    u64 mm = 0ULL;
#pragma unroll
    for (int j = 0; j < 20; j++)
      mm = fma2(Wm[i * 21 + j], Um[k * 21 + j], mm);
#pragma unroll
    for (int h = 0; h < 10; h++)
      accv[h] = fma2(mm, bc2(lin_w[h * 210 + t]), accv[h]);
  }
#pragma unroll
  for (int h = 0; h < 10; h++) {
    u64 v = accv[h];
    v = add2(v, __shfl_xor_sync(FULL, v, 16));
    v = add2(v, __shfl_xor_sync(FULL, v, 8));
    v = add2(v, __shfl_xor_sync(FULL, v, 4));
    v = add2(v, __shfl_xor_sync(FULL, v, 2));
    v = add2(v, __shfl_xor_sync(FULL, v, 1));
    accv[h] = v;
  }
  if (lane == 0) {
#pragma unroll
    for (int h = 0; h < 10; h++) {
      float vx, vy;
      up2(accv[h], vx, vy);
      const float bb = lin_b[h];
      out[b0 * 10 + h]      = vx + bb;
      out[b0 * 10 + 10 + h] = vy + bb;
    }
  }
}

// ---------------------------------------------------------------------------
extern "C" void kernel_launch(void* const* d_in, const int* in_sizes, int n_in,
                              void* d_out, int out_size) {
  const float* x  = (const float*)d_in[0];
  const float* W  = (const float*)d_in[1];
  const float* lw = (const float*)d_in[2];
  const float* lb = (const float*)d_in[3];
  float* out = (float*)d_out;

  cudaFuncSetAttribute(gram_kernel, cudaFuncAttributeMaxDynamicSharedMemorySize,
                       SMEM_BYTES);

  gram_kernel<<<4096, 256, SMEM_BYTES>>>(x, W);
  eig_kernel<<<512, 128>>>(lw, lb, out);
}